// round 2
// baseline (speedup 1.0000x reference)
#include <cuda_runtime.h>

// AdderNet 2D (K=3, S=1, P=1): out[n,f,y,x] = -sum_{c,i,j} |W[f,c,i,j] - xpad[n,c,y+i,x+j]|
// x: [8,64,32,32] f32, W: [64,64,3,3] f32, out: [8,64,32,32] f32.
//
// 512 threads/CTA: warp-half 0 (tid<256) accumulates channels [0,32),
// warp-half 1 channels [32,64); partials combined via smem reduction.

#define CIN   64
#define NFILT 64
#define HW    32
#define NIMG  8

#define FG    16              // filters per CTA (and per thread)
#define RT    8               // output rows per CTA
#define XROWS (RT + 2)        // padded rows in slab
#define XCOLS 34              // padded cols

#define SX_ELEMS (CIN * XROWS * XCOLS)   // 21760 floats = 87040 B
#define SW_ELEMS (CIN * 9 * FG)          // 9216 floats  = 36864 B
#define RED_ELEMS (256 * FG)             // 4096 floats  = 16384 B (as 2048 ull)
#define SMEM_BYTES ((SX_ELEMS + SW_ELEMS + RED_ELEMS) * 4)

typedef unsigned long long ull;

__global__ __launch_bounds__(512, 1)
void adder2d_kernel(const float* __restrict__ x,
                    const float* __restrict__ W,
                    float* __restrict__ out)
{
    extern __shared__ float smem[];
    float* sX = smem;                       // [c][r][col], padded with zeros
    float* sW = smem + SX_ELEMS;            // [k = c*9+i*3+j][ff], NEGATED weights
    ull*   sR = (ull*)(smem + SX_ELEMS + SW_ELEMS);  // [wtid][8 pairs] reduction buf

    const int tid  = threadIdx.x;           // 0..511
    const int half = tid >> 8;               // 0 / 1 : channel half
    const int wtid = tid & 255;              // position-id within half
    const int fg   = blockIdx.x;             // 0..3
    const int rt   = blockIdx.y;              // 0..3
    const int n    = blockIdx.z;               // 0..7
    const int y0   = rt * RT;
    const int f0   = fg * FG;

    // ---- load padded x slab (all 64 channels) ----
    const float* xn = x + (size_t)n * (CIN * HW * HW);
    for (int idx = tid; idx < SX_ELEMS; idx += 512) {
        int c   = idx / (XROWS * XCOLS);
        int rem = idx - c * (XROWS * XCOLS);
        int r   = rem / XCOLS;
        int col = rem - r * XCOLS;
        int gr  = y0 - 1 + r;
        int gc  = col - 1;
        float v = 0.0f;
        if ((unsigned)gr < HW && (unsigned)gc < HW)
            v = xn[(c * HW + gr) * HW + gc];
        sX[idx] = v;
    }

    // ---- load NEGATED weight tile: sW[k*FG + ff] = -W[(f0+ff)*576 + k] ----
    for (int idx = tid; idx < SW_ELEMS; idx += 512) {
        int ff = idx / (CIN * 9);
        int k  = idx - ff * (CIN * 9);
        sW[k * FG + ff] = -W[(f0 + ff) * (CIN * 9) + k];
    }
    __syncthreads();

    // ---- main loop: thread owns (y, col) x 16 filters over its 32 channels ----
    const int y    = wtid >> 5;              // 0..7
    const int col  = wtid & 31;              // 0..31
    const int cbeg = half * (CIN / 2);
    const int cend = cbeg + (CIN / 2);

    ull acc[FG / 2];
#pragma unroll
    for (int p = 0; p < FG / 2; p++) acc[p] = 0ULL;

#pragma unroll 1
    for (int c = cbeg; c < cend; c++) {
        const float* sxc = sX + c * (XROWS * XCOLS) + y * XCOLS + col;
        const float* swc = sW + c * 9 * FG;
#pragma unroll
        for (int i = 0; i < 3; i++) {
#pragma unroll
            for (int j = 0; j < 3; j++) {
                float xv = sxc[i * XCOLS + j];             // conflict-free LDS.32
                unsigned xr = __float_as_uint(xv);
                ull xx;
                asm("mov.b64 %0, {%1, %1};" : "=l"(xx) : "r"(xr));
                const ulonglong2* wrow =
                    (const ulonglong2*)(swc + (i * 3 + j) * FG);
#pragma unroll
                for (int q = 0; q < 4; q++) {              // 4x LDS.128 = 8 pairs
                    ulonglong2 w2 = wrow[q];               // broadcast (-W pair x2)
                    ull d0, d1;
                    asm("add.rn.f32x2 %0, %1, %2;" : "=l"(d0) : "l"(xx), "l"(w2.x));
                    asm("add.rn.f32x2 %0, %1, %2;" : "=l"(d1) : "l"(xx), "l"(w2.y));
                    d0 &= 0x7FFFFFFF7FFFFFFFULL;           // |.| both lanes
                    d1 &= 0x7FFFFFFF7FFFFFFFULL;
                    asm("add.rn.f32x2 %0, %0, %1;" : "+l"(acc[2*q])   : "l"(d0));
                    asm("add.rn.f32x2 %0, %0, %1;" : "+l"(acc[2*q+1]) : "l"(d1));
                }
            }
        }
    }

    // ---- combine the two channel halves ----
    __syncthreads();                         // sX/sW no longer needed after this point
    if (half == 1) {
#pragma unroll
        for (int p = 0; p < FG / 2; p++) sR[wtid * (FG / 2) + p] = acc[p];
    }
    __syncthreads();

    if (half == 0) {
        float* outp = out + (((size_t)n * NFILT + f0) * HW + (y0 + y)) * HW + col;
#pragma unroll
        for (int p = 0; p < FG / 2; p++) {
            ull other = sR[wtid * (FG / 2) + p];
            ull sum;
            asm("add.rn.f32x2 %0, %1, %2;" : "=l"(sum) : "l"(acc[p]), "l"(other));
            float lo = __uint_as_float((unsigned)(sum & 0xFFFFFFFFULL));
            float hi = __uint_as_float((unsigned)(sum >> 32));
            outp[(2 * p)     * (HW * HW)] = -lo;
            outp[(2 * p + 1) * (HW * HW)] = -hi;
        }
    }
}

extern "C" void kernel_launch(void* const* d_in, const int* in_sizes, int n_in,
                              void* d_out, int out_size)
{
    const float* x = (const float*)d_in[0];
    const float* W = (const float*)d_in[1];
    if (n_in >= 2 && in_sizes[0] == NFILT * CIN * 9 && in_sizes[1] == NIMG * CIN * HW * HW) {
        const float* t = x; x = W; W = t;
    }
    float* out = (float*)d_out;

    static int smem_set = -1;
    if (smem_set < 0) {
        cudaFuncSetAttribute(adder2d_kernel,
                             cudaFuncAttributeMaxDynamicSharedMemorySize, SMEM_BYTES);
        smem_set = 1;
    }

    dim3 grid(NFILT / FG, HW / RT, NIMG);   // 4 x 4 x 8 = 128 CTAs, one wave
    adder2d_kernel<<<grid, 512, SMEM_BYTES>>>(x, W, out);
}

// round 3
// speedup vs baseline: 1.0416x; 1.0416x over previous
#include <cuda_runtime.h>

// AdderNet 2D (K=3,S=1,P=1): out[n,f,y,x] = -sum_{c,i,j} |W[f,c,i,j] - xpad[n,c,y+i,x+j]|
// x: [8,64,32,32] f32, W: [64,64,3,3] f32, out: [8,64,32,32] f32.
//
// 512 threads/CTA = 128 position-workers (2 output rows each) x 4 channel-quarters.
// Negated weights in smem -> add.rn.f32x2 + 64-bit AND abs. One-time smem reduction.

#define CIN   64
#define NFILT 64
#define HW    32
#define NIMG  8

#define FG    16               // filters per CTA
#define RT    8                // output rows per CTA
#define XROWS (RT + 2)
#define XCOLS 34

#define SX_ELEMS (CIN * XROWS * XCOLS)   // 21760 f = 87040 B
#define SW_ELEMS (CIN * 9 * FG)          // 9216 f  = 36864 B
#define RED_ULL  (3 * 16 * 128)          // 3 quarters x 16 accs x 128 workers = 49152 B
#define SMEM_BYTES (SX_ELEMS * 4 + SW_ELEMS * 4 + RED_ULL * 8)

typedef unsigned long long ull;

__global__ __launch_bounds__(512, 1)
void adder2d_kernel(const float* __restrict__ x,
                    const float* __restrict__ W,
                    float* __restrict__ out)
{
    extern __shared__ float smem[];
    float* sX = smem;                        // [c][r 0..9][col 0..33], zero padded
    float* sW = smem + SX_ELEMS;             // [k=c*9+tap][ff], NEGATED weights
    ull*   sR = (ull*)(smem + SX_ELEMS + SW_ELEMS);  // [quarter-1][p 0..15][wk 0..127]

    const int tid = threadIdx.x;             // 0..511
    const int qtr = tid >> 7;                // 0..3 channel quarter
    const int wk  = tid & 127;               // worker: position pair
    const int yw  = wk >> 5;                 // 0..3 -> rows yw and yw+4
    const int col = wk & 31;
    const int fg  = blockIdx.x;              // 0..3
    const int rt  = blockIdx.y;              // 0..3
    const int n   = blockIdx.z;              // 0..7
    const int y0  = rt * RT;
    const int f0  = fg * FG;

    // ---- load padded x slab (all 64 channels) ----
    const float* xn = x + (size_t)n * (CIN * HW * HW);
    for (int idx = tid; idx < SX_ELEMS; idx += 512) {
        int c   = idx / (XROWS * XCOLS);
        int rem = idx - c * (XROWS * XCOLS);
        int r   = rem / XCOLS;
        int cc  = rem - r * XCOLS;
        int gr  = y0 - 1 + r;
        int gc  = cc - 1;
        float v = 0.0f;
        if ((unsigned)gr < HW && (unsigned)gc < HW)
            v = xn[(c * HW + gr) * HW + gc];
        sX[idx] = v;
    }
    // ---- NEGATED weights: sW[k*FG + ff] = -W[(f0+ff)*576 + k] ----
    for (int idx = tid; idx < SW_ELEMS; idx += 512) {
        int ff = idx / (CIN * 9);
        int k  = idx - ff * (CIN * 9);
        sW[k * FG + ff] = -W[(f0 + ff) * (CIN * 9) + k];
    }
    __syncthreads();

    ull acc[16];                              // [pos(2)][pair(8)] : pos0 = 0..7
#pragma unroll
    for (int p = 0; p < 16; p++) acc[p] = 0ULL;

    const int cbeg = qtr * (CIN / 4);

#pragma unroll 1
    for (int c = cbeg; c < cbeg + (CIN / 4); c++) {
        const float* sxc0 = sX + c * (XROWS * XCOLS) + yw * XCOLS + col;
        const float* sxc1 = sxc0 + 4 * XCOLS;
        const float* swc  = sW + c * 9 * FG;
#pragma unroll
        for (int i = 0; i < 3; i++) {
            // batch x loads for this kernel-row, both positions, packed lo==hi
            ull xa[3], xb[3];
#pragma unroll
            for (int j = 0; j < 3; j++) {
                unsigned ra = __float_as_uint(sxc0[i * XCOLS + j]);
                unsigned rb = __float_as_uint(sxc1[i * XCOLS + j]);
                asm("mov.b64 %0, {%1, %1};" : "=l"(xa[j]) : "r"(ra));
                asm("mov.b64 %0, {%1, %1};" : "=l"(xb[j]) : "r"(rb));
            }
#pragma unroll
            for (int q = 0; q < 4; q++) {
                // batch 3 weight LDS.128 (2 filter-pairs each), broadcast
                ulonglong2 w[3];
#pragma unroll
                for (int j = 0; j < 3; j++)
                    w[j] = *(const ulonglong2*)(swc + (i * 3 + j) * FG + q * 4);
#pragma unroll
                for (int j = 0; j < 3; j++) {
                    ull d;
                    asm("add.rn.f32x2 %0, %1, %2;" : "=l"(d) : "l"(xa[j]), "l"(w[j].x));
                    d &= 0x7FFFFFFF7FFFFFFFULL;
                    asm("add.rn.f32x2 %0, %0, %1;" : "+l"(acc[2*q]) : "l"(d));
                    asm("add.rn.f32x2 %0, %1, %2;" : "=l"(d) : "l"(xa[j]), "l"(w[j].y));
                    d &= 0x7FFFFFFF7FFFFFFFULL;
                    asm("add.rn.f32x2 %0, %0, %1;" : "+l"(acc[2*q+1]) : "l"(d));
                    asm("add.rn.f32x2 %0, %1, %2;" : "=l"(d) : "l"(xb[j]), "l"(w[j].x));
                    d &= 0x7FFFFFFF7FFFFFFFULL;
                    asm("add.rn.f32x2 %0, %0, %1;" : "+l"(acc[8+2*q]) : "l"(d));
                    asm("add.rn.f32x2 %0, %1, %2;" : "=l"(d) : "l"(xb[j]), "l"(w[j].y));
                    d &= 0x7FFFFFFF7FFFFFFFULL;
                    asm("add.rn.f32x2 %0, %0, %1;" : "+l"(acc[8+2*q+1]) : "l"(d));
                }
            }
        }
    }

    // ---- combine 4 channel quarters ----
    if (qtr != 0) {
        ull* buf = sR + (size_t)(qtr - 1) * (16 * 128);
#pragma unroll
        for (int p = 0; p < 16; p++) buf[p * 128 + wk] = acc[p];  // conflict-free
    }
    __syncthreads();

    if (qtr == 0) {
#pragma unroll
        for (int p = 0; p < 16; p++) {
            ull s = acc[p];
#pragma unroll
            for (int r = 0; r < 3; r++) {
                ull o = sR[(size_t)r * (16 * 128) + p * 128 + wk];
                asm("add.rn.f32x2 %0, %0, %1;" : "+l"(s) : "l"(o));
            }
            acc[p] = s;
        }
        // ---- write: 2 rows x 16 filters, negate ----
#pragma unroll
        for (int pos = 0; pos < 2; pos++) {
            int gy = y0 + yw + pos * 4;
            float* outp = out + (((size_t)n * NFILT + f0) * HW + gy) * HW + col;
#pragma unroll
            for (int pp = 0; pp < 8; pp++) {
                ull s = acc[pos * 8 + pp];
                float lo = __uint_as_float((unsigned)(s & 0xFFFFFFFFULL));
                float hi = __uint_as_float((unsigned)(s >> 32));
                outp[(2 * pp)     * (HW * HW)] = -lo;
                outp[(2 * pp + 1) * (HW * HW)] = -hi;
            }
        }
    }
}

extern "C" void kernel_launch(void* const* d_in, const int* in_sizes, int n_in,
                              void* d_out, int out_size)
{
    const float* x = (const float*)d_in[0];
    const float* W = (const float*)d_in[1];
    if (n_in >= 2 && in_sizes[0] == NFILT * CIN * 9 && in_sizes[1] == NIMG * CIN * HW * HW) {
        const float* t = x; x = W; W = t;
    }
    float* out = (float*)d_out;

    static int smem_set = -1;
    if (smem_set < 0) {
        cudaFuncSetAttribute(adder2d_kernel,
                             cudaFuncAttributeMaxDynamicSharedMemorySize, SMEM_BYTES);
        smem_set = 1;
    }

    dim3 grid(NFILT / FG, HW / RT, NIMG);   // 4 x 4 x 8 = 128 CTAs, one wave
    adder2d_kernel<<<grid, 512, SMEM_BYTES>>>(x, W, out);
}

// round 4
// speedup vs baseline: 1.0593x; 1.0171x over previous
#include <cuda_runtime.h>

// AdderNet 2D (K=3,S=1,P=1): out[n,f,y,x] = -sum_{c,i,j} |W[f,c,i,j] - xpad[n,c,y+i,x+j]|
// x: [8,64,32,32] f32, W: [64,64,3,3] f32, out: [8,64,32,32] f32.
//
// 512 threads/CTA = 128 position-workers (2 rows each) x 4 channel-quarters.
// Per (c,i) stage: batch-issue 12 weight LDS.128 + 6 x LDS.32 (MLP=18), then
// 192 core ops consumed in load order -> LDS latency almost fully hidden.

#define CIN   64
#define NFILT 64
#define HW    32
#define NIMG  8

#define FG    16
#define RT    8
#define XROWS (RT + 2)
#define XCOLS 34

#define SX_ELEMS (CIN * XROWS * XCOLS)   // 21760 f = 87040 B
#define SW_ELEMS (CIN * 9 * FG)          // 9216 f  = 36864 B
// reduction buffer (3 * 16 * 128 ull = 48KB) aliases sX (dead after main loop)
#define SMEM_BYTES ((SX_ELEMS + SW_ELEMS) * 4)

typedef unsigned long long ull;

__global__ __launch_bounds__(512, 1)
void adder2d_kernel(const float* __restrict__ x,
                    const float* __restrict__ W,
                    float* __restrict__ out)
{
    extern __shared__ float smem[];
    float* sX = smem;                        // [c][r 0..9][col 0..33], zero padded
    float* sW = smem + SX_ELEMS;             // [k=c*9+tap][ff], NEGATED weights
    ull*   sR = (ull*)smem;                  // aliases sX after main loop

    const int tid = threadIdx.x;             // 0..511
    const int qtr = tid >> 7;                // 0..3 channel quarter
    const int wk  = tid & 127;               // worker: position pair
    const int yw  = wk >> 5;                 // rows yw and yw+4
    const int col = wk & 31;
    const int fg  = blockIdx.x;
    const int rt  = blockIdx.y;
    const int n   = blockIdx.z;
    const int y0  = rt * RT;
    const int f0  = fg * FG;

    // ---- load padded x slab (all 64 channels) ----
    const float* xn = x + (size_t)n * (CIN * HW * HW);
    for (int idx = tid; idx < SX_ELEMS; idx += 512) {
        int c   = idx / (XROWS * XCOLS);
        int rem = idx - c * (XROWS * XCOLS);
        int r   = rem / XCOLS;
        int cc  = rem - r * XCOLS;
        int gr  = y0 - 1 + r;
        int gc  = cc - 1;
        float v = 0.0f;
        if ((unsigned)gr < HW && (unsigned)gc < HW)
            v = xn[(c * HW + gr) * HW + gc];
        sX[idx] = v;
    }
    // ---- NEGATED weights: sW[k*FG + ff] = -W[(f0+ff)*576 + k] ----
    for (int idx = tid; idx < SW_ELEMS; idx += 512) {
        int ff = idx / (CIN * 9);
        int k  = idx - ff * (CIN * 9);
        sW[k * FG + ff] = -W[(f0 + ff) * (CIN * 9) + k];
    }
    __syncthreads();

    ull acc[16];                              // [pos(2)][pair(8)]
#pragma unroll
    for (int p = 0; p < 16; p++) acc[p] = 0ULL;

    const int cbeg = qtr * (CIN / 4);

#pragma unroll 1
    for (int c = cbeg; c < cbeg + (CIN / 4); c++) {
        const float* sxc0 = sX + c * (XROWS * XCOLS) + yw * XCOLS + col;
        const float* swc  = sW + c * 9 * FG;
#pragma unroll
        for (int i = 0; i < 3; i++) {
            // ---- batch-issue ALL loads for this (c,i) stage: MLP = 18 ----
            float fa0 = sxc0[i * XCOLS + 0];
            float fa1 = sxc0[i * XCOLS + 1];
            float fa2 = sxc0[i * XCOLS + 2];
            float fb0 = sxc0[(i + 4) * XCOLS + 0];
            float fb1 = sxc0[(i + 4) * XCOLS + 1];
            float fb2 = sxc0[(i + 4) * XCOLS + 2];
            ulonglong2 w[12];                 // [q][j], load order == consume order
#pragma unroll
            for (int q = 0; q < 4; q++)
#pragma unroll
                for (int j = 0; j < 3; j++)
                    w[q * 3 + j] = *(const ulonglong2*)(swc + (i * 3 + j) * FG + q * 4);

            ull xa[3], xb[3];
            asm("mov.b64 %0, {%1, %1};" : "=l"(xa[0]) : "r"(__float_as_uint(fa0)));
            asm("mov.b64 %0, {%1, %1};" : "=l"(xa[1]) : "r"(__float_as_uint(fa1)));
            asm("mov.b64 %0, {%1, %1};" : "=l"(xa[2]) : "r"(__float_as_uint(fa2)));
            asm("mov.b64 %0, {%1, %1};" : "=l"(xb[0]) : "r"(__float_as_uint(fb0)));
            asm("mov.b64 %0, {%1, %1};" : "=l"(xb[1]) : "r"(__float_as_uint(fb1)));
            asm("mov.b64 %0, {%1, %1};" : "=l"(xb[2]) : "r"(__float_as_uint(fb2)));

            // ---- 192 core ops, consuming w[] in load order ----
#pragma unroll
            for (int q = 0; q < 4; q++) {
#pragma unroll
                for (int j = 0; j < 3; j++) {
                    const ulonglong2 wv = w[q * 3 + j];
                    ull d;
                    asm("add.rn.f32x2 %0, %1, %2;" : "=l"(d) : "l"(xa[j]), "l"(wv.x));
                    d &= 0x7FFFFFFF7FFFFFFFULL;
                    asm("add.rn.f32x2 %0, %0, %1;" : "+l"(acc[2*q]) : "l"(d));
                    asm("add.rn.f32x2 %0, %1, %2;" : "=l"(d) : "l"(xa[j]), "l"(wv.y));
                    d &= 0x7FFFFFFF7FFFFFFFULL;
                    asm("add.rn.f32x2 %0, %0, %1;" : "+l"(acc[2*q+1]) : "l"(d));
                    asm("add.rn.f32x2 %0, %1, %2;" : "=l"(d) : "l"(xb[j]), "l"(wv.x));
                    d &= 0x7FFFFFFF7FFFFFFFULL;
                    asm("add.rn.f32x2 %0, %0, %1;" : "+l"(acc[8+2*q]) : "l"(d));
                    asm("add.rn.f32x2 %0, %1, %2;" : "=l"(d) : "l"(xb[j]), "l"(wv.y));
                    d &= 0x7FFFFFFF7FFFFFFFULL;
                    asm("add.rn.f32x2 %0, %0, %1;" : "+l"(acc[8+2*q+1]) : "l"(d));
                }
            }
        }
    }

    // ---- combine 4 channel quarters (sR aliases sX, now dead) ----
    __syncthreads();
    if (qtr != 0) {
        ull* buf = sR + (size_t)(qtr - 1) * (16 * 128);
#pragma unroll
        for (int p = 0; p < 16; p++) buf[p * 128 + wk] = acc[p];
    }
    __syncthreads();

    if (qtr == 0) {
#pragma unroll
        for (int p = 0; p < 16; p++) {
            ull s = acc[p];
#pragma unroll
            for (int r = 0; r < 3; r++) {
                ull o = sR[(size_t)r * (16 * 128) + p * 128 + wk];
                asm("add.rn.f32x2 %0, %0, %1;" : "+l"(s) : "l"(o));
            }
            acc[p] = s;
        }
#pragma unroll
        for (int pos = 0; pos < 2; pos++) {
            int gy = y0 + yw + pos * 4;
            float* outp = out + (((size_t)n * NFILT + f0) * HW + gy) * HW + col;
#pragma unroll
            for (int pp = 0; pp < 8; pp++) {
                ull s = acc[pos * 8 + pp];
                float lo = __uint_as_float((unsigned)(s & 0xFFFFFFFFULL));
                float hi = __uint_as_float((unsigned)(s >> 32));
                outp[(2 * pp)     * (HW * HW)] = -lo;
                outp[(2 * pp + 1) * (HW * HW)] = -hi;
            }
        }
    }
}

extern "C" void kernel_launch(void* const* d_in, const int* in_sizes, int n_in,
                              void* d_out, int out_size)
{
    const float* x = (const float*)d_in[0];
    const float* W = (const float*)d_in[1];
    if (n_in >= 2 && in_sizes[0] == NFILT * CIN * 9 && in_sizes[1] == NIMG * CIN * HW * HW) {
        const float* t = x; x = W; W = t;
    }
    float* out = (float*)d_out;

    static int smem_set = -1;
    if (smem_set < 0) {
        cudaFuncSetAttribute(adder2d_kernel,
                             cudaFuncAttributeMaxDynamicSharedMemorySize, SMEM_BYTES);
        smem_set = 1;
    }

    dim3 grid(NFILT / FG, HW / RT, NIMG);   // 128 CTAs
    adder2d_kernel<<<grid, 512, SMEM_BYTES>>>(x, W, out);
}